// round 15
// baseline (speedup 1.0000x reference)
#include <cuda_runtime.h>
#include <cuda_fp16.h>
#include <math.h>
#include <stdint.h>

// B=2, T=2048, D=3584, N=16, K=8, H=256, WINDOW=1024, SOFT_CAP=50, SCALAR=0.0625

// ---------------- scratch (allocation-free device globals) -------------------
__device__ unsigned short g_Xh  [4096u * 3584u];  // x fp16
__device__ unsigned short g_Wth [8192u * 3584u];  // qkv weight [j][d] K-major fp16
__device__ unsigned short g_OWth[3584u * 4096u];  // o_w^T [d][j] K-major fp16
__device__ unsigned short g_QKVh[4096u * 8192u];  // [B*T][ q | k | v ] fp16
__device__ unsigned short g_ENCh[4096u * 4096u];  // attention output fp16
__device__ float          g_ts  [128];            // RoPE timescales (powf table)

// ---------------- helpers -----------------------------------------------------
__device__ __forceinline__ uint32_t smem_u32(const void* p) {
    uint32_t a;
    asm("{ .reg .u64 t; cvta.to.shared.u64 t, %1; cvt.u32.u64 %0, t; }" : "=r"(a) : "l"(p));
    return a;
}
__device__ __forceinline__ void ldsm4(uint32_t* d, uint32_t addr) {
    asm volatile("ldmatrix.sync.aligned.m8n8.x4.shared.b16 {%0,%1,%2,%3}, [%4];"
                 : "=r"(d[0]), "=r"(d[1]), "=r"(d[2]), "=r"(d[3]) : "r"(addr));
}
__device__ __forceinline__ void ldsm4t(uint32_t* d, uint32_t addr) {
    asm volatile("ldmatrix.sync.aligned.m8n8.x4.trans.shared.b16 {%0,%1,%2,%3}, [%4];"
                 : "=r"(d[0]), "=r"(d[1]), "=r"(d[2]), "=r"(d[3]) : "r"(addr));
}
__device__ __forceinline__ void mma16816(float* c, const uint32_t* a, uint32_t b0, uint32_t b1) {
    asm volatile("mma.sync.aligned.m16n8k16.row.col.f32.f16.f16.f32 "
                 "{%0,%1,%2,%3}, {%4,%5,%6,%7}, {%8,%9}, {%0,%1,%2,%3};"
                 : "+f"(c[0]), "+f"(c[1]), "+f"(c[2]), "+f"(c[3])
                 : "r"(a[0]), "r"(a[1]), "r"(a[2]), "r"(a[3]), "r"(b0), "r"(b1));
}
__device__ __forceinline__ uint32_t f22u(float a, float b) {
    __half2 h = __floats2half2_rn(a, b);
    return *(uint32_t*)&h;
}
__device__ __forceinline__ void cpa16(uint32_t dst, const void* src) {
    asm volatile("cp.async.cg.shared.global [%0], [%1], 16;" :: "r"(dst), "l"(src));
}

// ---------------- fused prep: conv_x + pack_wt + pack_owt + ts table ----------
__global__ __launch_bounds__(256) void prep_all(const float* __restrict__ x,
                                                const float* __restrict__ qw,
                                                const float* __restrict__ kvw,
                                                const float* __restrict__ ow)
{
    __shared__ float t[32][33];
    const int blk = blockIdx.x;
    const int c  = threadIdx.x & 31;
    const int r0 = threadIdx.x >> 5;

    if (blk < 14336) {
        size_t i = ((size_t)blk * 256 + threadIdx.x) * 4;
        float4 v = *(const float4*)(x + i);
        uint2 u = make_uint2(f22u(v.x, v.y), f22u(v.z, v.w));
        *(uint2*)((__half*)g_Xh + i) = u;
    } else if (blk < 43008) {
        int lin = blk - 14336;
        int hd  = lin / 896;
        int rem = lin - hd * 896;
        int h0  = (rem / 112) << 5;
        int d0  = (rem % 112) << 5;
        const float* src = (hd < 16) ? (qw + (size_t)hd * 3584 * 256)
                                     : (kvw + (size_t)(hd - 16) * 3584 * 256);
#pragma unroll
        for (int r = r0; r < 32; r += 8)
            t[r][c] = src[(size_t)(d0 + r) * 256 + h0 + c];
        __syncthreads();
#pragma unroll
        for (int r = r0; r < 32; r += 8)
            g_Wth[(size_t)(hd * 256 + h0 + r) * 3584 + d0 + c] =
                __half_as_ushort(__float2half(t[c][r]));
    } else if (blk < 57344) {
        int lin = blk - 43008;
        int j0  = (lin % 128) << 5;
        int d0  = (lin / 128) << 5;
#pragma unroll
        for (int r = r0; r < 32; r += 8)
            t[r][c] = ow[(size_t)(j0 + r) * 3584 + d0 + c];
        __syncthreads();
#pragma unroll
        for (int r = r0; r < 32; r += 8)
            g_OWth[(size_t)(d0 + r) * 4096 + j0 + c] =
                __half_as_ushort(__float2half(t[c][r]));
    } else {
        int i = threadIdx.x;
        if (i < 128)
            g_ts[i] = powf(10000.0f, (float)i * (1.0f / 128.0f));
    }
}

// ------ fp16 HMMA GEMM: R14 config (128x128 CTA, 32x64 warp, 4-stage, supertile)
#define PITCH 40
#define STAGE_B 20480
#define NSTG 4
#define HGEMM_SMEM (NSTG * STAGE_B)      // 81920 B -> 2 CTAs/SM

template <typename CT>
__global__ __launch_bounds__(256, 2) void hgemm(const __half* __restrict__ A,
                                                const __half* __restrict__ B,
                                                CT* __restrict__ C,
                                                int Nout, int Kdim)
{
    extern __shared__ __half hsm[];

    const int tid  = threadIdx.x;
    const int lane = tid & 31;
    const int wid  = tid >> 5;
    const int wm = (wid & 3) << 5;
    const int wn = (wid >> 2) << 6;

    const int lin = blockIdx.y * gridDim.x + blockIdx.x;
    const int tpg = gridDim.x << 3;
    const int grp = lin / tpg;
    const int rem = lin - grp * tpg;
    const int m0 = ((grp << 3) + (rem & 7)) << 7;
    const int n0 = (rem >> 3) << 7;

    const int nk = Kdim >> 5;

    const int lrow = tid >> 1;
    const int lcol = (tid & 1) << 4;
    const __half* ag = A + (size_t)(m0 + lrow) * Kdim + lcol;
    const __half* bg = B + (size_t)(n0 + lrow) * Kdim + lcol;

    uint32_t sb  = smem_u32(hsm);
    uint32_t sa  = sb + (uint32_t)(lrow * PITCH + lcol) * 2;
    uint32_t sbq = sa + 10240;

    const uint32_t lq = lane & 15;
    const uint32_t lh = (lane >> 4) << 4;
    uint32_t abase = sb + ((wm + lq) * PITCH) * 2 + lh;
    uint32_t bbase = sb + 10240 + ((wn + lq) * PITCH) * 2 + lh;

    float acc[2][8][4];
#pragma unroll
    for (int i = 0; i < 2; i++)
#pragma unroll
        for (int j = 0; j < 8; j++)
#pragma unroll
            for (int q = 0; q < 4; q++) acc[i][j][q] = 0.f;

#define HLOAD(i, s) do {                                                          \
    uint32_t _da = sa + (uint32_t)(s) * STAGE_B;                                  \
    uint32_t _db = sbq + (uint32_t)(s) * STAGE_B;                                 \
    const __half* _a = ag + ((i) << 5);                                           \
    const __half* _b = bg + ((i) << 5);                                           \
    asm volatile("cp.async.cg.shared.global [%0], [%1], 16;\n\t"                  \
                 "cp.async.cg.shared.global [%2], [%3], 16;\n\t"                  \
                 "cp.async.cg.shared.global [%4], [%5], 16;\n\t"                  \
                 "cp.async.cg.shared.global [%6], [%7], 16;\n\t"                  \
                 "cp.async.commit_group;"                                         \
                 :: "r"(_da), "l"(_a), "r"(_da + 16), "l"(_a + 8),                \
                    "r"(_db), "l"(_b), "r"(_db + 16), "l"(_b + 8));               \
} while (0)

    HLOAD(0, 0);
    HLOAD(1, 1);
    HLOAD(2, 2);

    for (int i = 0; i < nk; i++) {
        if (i < nk - 2)       asm volatile("cp.async.wait_group 2;");
        else if (i == nk - 2) asm volatile("cp.async.wait_group 1;");
        else                  asm volatile("cp.async.wait_group 0;");
        __syncthreads();
        if (i + 3 < nk) HLOAD(i + 3, (i + 3) & 3);

        uint32_t so = (uint32_t)(i & 3) * STAGE_B;
        uint32_t ab = abase + so;
        uint32_t bb = bbase + so;
#pragma unroll
        for (int ks = 0; ks < 2; ks++) {
            uint32_t af[2][4], bf[4][4];
            ldsm4(af[0], ab + ks * 32);
            ldsm4(af[1], ab + 16 * PITCH * 2 + ks * 32);
#pragma unroll
            for (int p = 0; p < 4; p++)
                ldsm4(bf[p], bb + p * (16 * PITCH * 2) + ks * 32);
#pragma unroll
            for (int mt = 0; mt < 2; mt++)
#pragma unroll
                for (int p = 0; p < 4; p++) {
                    mma16816(acc[mt][2 * p],     af[mt], bf[p][0], bf[p][2]);
                    mma16816(acc[mt][2 * p + 1], af[mt], bf[p][1], bf[p][3]);
                }
        }
    }

    const int g  = lane >> 2;
    const int cc = (lane & 3) << 1;
#pragma unroll
    for (int mt = 0; mt < 2; mt++) {
        int r = m0 + wm + mt * 16 + g;
#pragma unroll
        for (int nt = 0; nt < 8; nt++) {
            size_t off = (size_t)r * Nout + n0 + wn + nt * 8 + cc;
            if (sizeof(CT) == 2) {
                __half* cp = (__half*)C + off;
                *(uint32_t*)cp = f22u(acc[mt][nt][0], acc[mt][nt][1]);
                *(uint32_t*)(cp + (size_t)8 * Nout) = f22u(acc[mt][nt][2], acc[mt][nt][3]);
            } else {
                float* cp = (float*)C + off;
                *(float2*)cp = make_float2(acc[mt][nt][0], acc[mt][nt][1]);
                *(float2*)(cp + (size_t)8 * Nout) = make_float2(acc[mt][nt][2], acc[mt][nt][3]);
            }
        }
    }
}

// ---------------- RoPE for K heads only (q-RoPE fused into attention) ---------
__global__ __launch_bounds__(128) void rope_k_kernel(const int* __restrict__ segpos)
{
    int bt = blockIdx.x;
    int hh = 16 + blockIdx.y;             // k heads: 16..23
    int i  = threadIdx.x;
    __half* p = (__half*)g_QKVh + (size_t)bt * 8192 + hh * 256;
    float pos = (float)segpos[bt];
    float ts  = g_ts[i];
    float ang = pos / ts;
    float s, c;
    sincosf(ang, &s, &c);
    float a  = __half2float(p[i]);
    float b2 = __half2float(p[i + 128]);
    p[i]       = __float2half(a * c - b2 * s);
    p[i + 128] = __float2half(b2 * c + a * s);
}

// ---------------- fp16 tensor-core flash attention + fused Q-RoPE -------------
#define APITCH 264
#define KS_OFF (128 * APITCH)
#define KS_SZ  (64 * APITCH)
#define VS_OFF (KS_OFF + 2 * KS_SZ)
#define ATTN_SMEM ((KS_OFF + 4 * KS_SZ) * 2)   // 202752 bytes

__global__ __launch_bounds__(256, 1) void attn_kernel(const int* __restrict__ segpos)
{
    extern __shared__ __half ash[];
    const int tid  = threadIdx.x;
    const int lane = tid & 31;
    const int w    = tid >> 5;
    const int t0   = (15 - blockIdx.x) << 7;   // heavy tiles scheduled first
    const int n    = blockIdx.y;
    const int b    = blockIdx.z;
    const int kh   = n >> 1;
    uint32_t sb = smem_u32(ash);

    const __half* qkvh = (const __half*)g_QKVh + (size_t)b * 2048 * 8192;

    int smin = t0 - 1023; if (smin < 0) smin = 0;
    const int c0 = smin >> 6, c1 = (t0 + 127) >> 6;

    const int ldr = tid >> 5, ldc = (tid & 31) << 3;

#define LOADKV(sg0, bf) do {                                                       \
    const __half* _ks = qkvh + (size_t)(sg0) * 8192 + 4096 + kh * 256;             \
    uint32_t _kb = sb + (KS_OFF + (bf) * KS_SZ) * 2;                               \
    uint32_t _vb = sb + (VS_OFF + (bf) * KS_SZ) * 2;                               \
    _Pragma("unroll")                                                              \
    for (int _it = 0; _it < 8; _it++) {                                            \
        int _r = _it * 8 + ldr;                                                    \
        cpa16(_kb + (_r * APITCH + ldc) * 2, _ks + (size_t)_r * 8192 + ldc);       \
        cpa16(_vb + (_r * APITCH + ldc) * 2, _ks + (size_t)_r * 8192 + 2048 + ldc);\
    }                                                                              \
    asm volatile("cp.async.commit_group;");                                        \
} while (0)

    // kick off chunk-0 K/V prefetch FIRST, then do Q rope under it
    LOADKV(c0 << 6, 0);

    // Q tile: load fp16 q, apply RoPE + 0.0625 scale (identical math to the old
    // rope kernel: same g_ts, pos/ts, sincosf, fp32 rotate, fp16 round), STS.
    {
        const __half* qs = qkvh + (size_t)t0 * 8192 + n * 256;
        const int* sp = segpos + b * 2048 + t0;
        __half* qsm = ash;
#pragma unroll
        for (int it = 0; it < 8; it++) {
            int slot = it * 256 + tid;        // 2048 slots: 128 rows x 16 col-groups
            int r  = slot >> 4;
            int g8 = (slot & 15) << 3;        // first-half col group: 0..120
            const __half* qp = qs + (size_t)r * 8192;
            float pos = (float)sp[r];
            uint4 ua = *(const uint4*)(qp + g8);         // cols g8..g8+7
            uint4 ub = *(const uint4*)(qp + g8 + 128);   // cols g8+128..
            uint32_t oa[4], ob[4];
            const uint32_t* pa = (const uint32_t*)&ua;
            const uint32_t* pb = (const uint32_t*)&ub;
#pragma unroll
            for (int j = 0; j < 4; j++) {
                __half2 a2 = *(const __half2*)&pa[j];
                __half2 b2 = *(const __half2*)&pb[j];
                int i0 = g8 + 2 * j;
                float s0, c0s, s1, c1s;
                sincosf(pos / g_ts[i0],     &s0, &c0s);
                sincosf(pos / g_ts[i0 + 1], &s1, &c1s);
                float a0 = __low2float(a2), a1 = __high2float(a2);
                float b0 = __low2float(b2), b1 = __high2float(b2);
                oa[j] = f22u((a0 * c0s - b0 * s0) * 0.0625f,
                             (a1 * c1s - b1 * s1) * 0.0625f);
                ob[j] = f22u((b0 * c0s + a0 * s0) * 0.0625f,
                             (b1 * c1s + a1 * s1) * 0.0625f);
            }
            *(uint4*)(qsm + r * APITCH + g8)       = make_uint4(oa[0], oa[1], oa[2], oa[3]);
            *(uint4*)(qsm + r * APITCH + g8 + 128) = make_uint4(ob[0], ob[1], ob[2], ob[3]);
        }
    }

    float of[32][4];
#pragma unroll
    for (int f = 0; f < 32; f++)
#pragma unroll
        for (int q = 0; q < 4; q++) of[f][q] = 0.f;
    float m0 = -1e30f, m1 = -1e30f, l0 = 0.f, l1 = 0.f;

    const uint32_t lq  = lane & 15;
    const uint32_t lh16 = (lane >> 4) << 4;
    uint32_t qb  = sb + (((w << 4) + lq) * APITCH) * 2 + lh16;
    uint32_t kvl = (lq * APITCH) * 2 + lh16;

    const int row0 = t0 + (w << 4) + (lane >> 2);
    const int row1 = row0 + 8;
    const int colq = (lane & 3) << 1;
    const int wr0 = t0 + (w << 4), wr1 = wr0 + 15;

    int buf = 0;
    for (int c = c0; c <= c1; c++) {
        const int sg0 = c << 6;
        if (c < c1) {
            LOADKV((c + 1) << 6, buf ^ 1);
            asm volatile("cp.async.wait_group 1;");
        } else {
            asm volatile("cp.async.wait_group 0;");
        }
        __syncthreads();

        if (sg0 <= wr1 && sg0 + 63 >= wr0 - 1023) {
            uint32_t kb = sb + (KS_OFF + buf * KS_SZ) * 2 + kvl;
            uint32_t vb = sb + (VS_OFF + buf * KS_SZ) * 2 + kvl;

            float sf[8][4];
#pragma unroll
            for (int j = 0; j < 8; j++)
#pragma unroll
                for (int q = 0; q < 4; q++) sf[j][q] = 0.f;

#pragma unroll
            for (int kk = 0; kk < 16; kk++) {
                uint32_t a[4];
                ldsm4(a, qb + kk * 32);
#pragma unroll
                for (int ng = 0; ng < 4; ng++) {
                    uint32_t bfr[4];
                    ldsm4(bfr, kb + ng * (16 * APITCH * 2) + kk * 32);
                    mma16816(sf[ng * 2],     a, bfr[0], bfr[2]);
                    mma16816(sf[ng * 2 + 1], a, bfr[1], bfr[3]);
                }
            }

            float mx0 = -1e30f, mx1 = -1e30f;
#pragma unroll
            for (int j = 0; j < 8; j++) {
                int col = sg0 + j * 8 + colq;
#pragma unroll
                for (int q = 0; q < 4; q++) {
                    float e = __expf(sf[j][q] * 0.04f);
                    float s = 50.f * __fdividef(e - 1.f, e + 1.f);
                    int rr = (q < 2) ? row0 : row1;
                    int cc2 = col + (q & 1);
                    bool ok = (cc2 <= rr) && (cc2 >= rr - 1023);
                    sf[j][q] = ok ? s : -1e30f;
                }
                mx0 = fmaxf(mx0, fmaxf(sf[j][0], sf[j][1]));
                mx1 = fmaxf(mx1, fmaxf(sf[j][2], sf[j][3]));
            }
            mx0 = fmaxf(mx0, __shfl_xor_sync(~0u, mx0, 1));
            mx0 = fmaxf(mx0, __shfl_xor_sync(~0u, mx0, 2));
            mx1 = fmaxf(mx1, __shfl_xor_sync(~0u, mx1, 1));
            mx1 = fmaxf(mx1, __shfl_xor_sync(~0u, mx1, 2));

            float mn0 = fmaxf(m0, mx0), mn1 = fmaxf(m1, mx1);
            float a0 = __expf(m0 - mn0), a1 = __expf(m1 - mn1);
            m0 = mn0; m1 = mn1;

            float rs0 = 0.f, rs1 = 0.f;
#pragma unroll
            for (int j = 0; j < 8; j++) {
                sf[j][0] = __expf(sf[j][0] - mn0); rs0 += sf[j][0];
                sf[j][1] = __expf(sf[j][1] - mn0); rs0 += sf[j][1];
                sf[j][2] = __expf(sf[j][2] - mn1); rs1 += sf[j][2];
                sf[j][3] = __expf(sf[j][3] - mn1); rs1 += sf[j][3];
            }
            rs0 += __shfl_xor_sync(~0u, rs0, 1);
            rs0 += __shfl_xor_sync(~0u, rs0, 2);
            rs1 += __shfl_xor_sync(~0u, rs1, 1);
            rs1 += __shfl_xor_sync(~0u, rs1, 2);
            l0 = l0 * a0 + rs0;
            l1 = l1 * a1 + rs1;

#pragma unroll
            for (int f = 0; f < 32; f++) {
                of[f][0] *= a0; of[f][1] *= a0;
                of[f][2] *= a1; of[f][3] *= a1;
            }

            uint32_t pa2[4][4];
#pragma unroll
            for (int sj = 0; sj < 4; sj++) {
                pa2[sj][0] = f22u(sf[2 * sj][0],     sf[2 * sj][1]);
                pa2[sj][1] = f22u(sf[2 * sj][2],     sf[2 * sj][3]);
                pa2[sj][2] = f22u(sf[2 * sj + 1][0], sf[2 * sj + 1][1]);
                pa2[sj][3] = f22u(sf[2 * sj + 1][2], sf[2 * sj + 1][3]);
            }

#pragma unroll
            for (int sj = 0; sj < 4; sj++) {
#pragma unroll
                for (int hg = 0; hg < 16; hg++) {
                    uint32_t v[4];
                    ldsm4t(v, vb + sj * (16 * APITCH * 2) + hg * 32);
                    mma16816(of[hg * 2],     pa2[sj], v[0], v[1]);
                    mma16816(of[hg * 2 + 1], pa2[sj], v[2], v[3]);
                }
            }
        }
        __syncthreads();
        buf ^= 1;
    }

    float i0 = 1.f / l0, i1 = 1.f / l1;
    __half* ENC = (__half*)g_ENCh;
    size_t base0 = ((size_t)(b * 2048) + row0) * 4096 + n * 256 + colq;
    size_t base1 = ((size_t)(b * 2048) + row1) * 4096 + n * 256 + colq;
#pragma unroll
    for (int f = 0; f < 32; f++) {
        *(uint32_t*)(ENC + base0 + f * 8) = f22u(of[f][0] * i0, of[f][1] * i0);
        *(uint32_t*)(ENC + base1 + f * 8) = f22u(of[f][2] * i1, of[f][3] * i1);
    }
}

// ---------------- launch (single-stream schedule) -------------------------------
extern "C" void kernel_launch(void* const* d_in, const int* in_sizes, int n_in,
                              void* d_out, int out_size)
{
    const float* x      = (const float*)d_in[0];
    const int*   segpos = (const int*)  d_in[1];
    const float* qw     = (const float*)d_in[3];
    const float* kvw    = (const float*)d_in[4];
    const float* ow     = (const float*)d_in[5];
    float* out = (float*)d_out;

    void *Xh, *Wth, *OWth, *QKVh, *ENCh;
    cudaGetSymbolAddress(&Xh,   g_Xh);
    cudaGetSymbolAddress(&Wth,  g_Wth);
    cudaGetSymbolAddress(&OWth, g_OWth);
    cudaGetSymbolAddress(&QKVh, g_QKVh);
    cudaGetSymbolAddress(&ENCh, g_ENCh);

    // fused prep: conv_x + pack_wt + pack_owt + ts table (one launch)
    prep_all<<<57345, 256>>>(x, qw, kvw, ow);

    cudaFuncSetAttribute(hgemm<__half>, cudaFuncAttributeMaxDynamicSharedMemorySize, HGEMM_SMEM);
    cudaFuncSetAttribute(hgemm<float>,  cudaFuncAttributeMaxDynamicSharedMemorySize, HGEMM_SMEM);
    cudaFuncSetAttribute(attn_kernel,   cudaFuncAttributeMaxDynamicSharedMemorySize, ATTN_SMEM);

    // qkv = x @ Wt^T -> fp16  (M=4096, N=8192, K=3584)
    hgemm<__half><<<dim3(8192 / 128, 4096 / 128), 256, HGEMM_SMEM>>>(
        (const __half*)Xh, (const __half*)Wth, (__half*)QKVh, 8192, 3584);

    // RoPE on K heads only (q-RoPE fused into attention prologue)
    rope_k_kernel<<<dim3(4096, 8), 128>>>(segpos);

    // fp16 flash attention (with fused Q-RoPE + scale) -> ENCh
    attn_kernel<<<dim3(16, 16, 2), 256, ATTN_SMEM>>>(segpos);

    // out = ENC @ OWt^T -> fp32  (M=4096, N=3584, K=4096)
    hgemm<float><<<dim3(3584 / 128, 4096 / 128), 256, HGEMM_SMEM>>>(
        (const __half*)ENCh, (const __half*)OWth, out, 3584, 4096);
}

// round 16
// speedup vs baseline: 1.0263x; 1.0263x over previous
#include <cuda_runtime.h>
#include <cuda_fp16.h>
#include <math.h>
#include <stdint.h>

// B=2, T=2048, D=3584, N=16, K=8, H=256, WINDOW=1024, SOFT_CAP=50, SCALAR=0.0625

// ---------------- scratch (allocation-free device globals) -------------------
__device__ unsigned short g_Xh  [4096u * 3584u];  // x fp16
__device__ unsigned short g_Wth [8192u * 3584u];  // qkv weight [j][d] K-major fp16
__device__ unsigned short g_OWth[3584u * 4096u];  // o_w^T [d][j] K-major fp16
__device__ unsigned short g_QKVh[4096u * 8192u];  // [B*T][ q | k | v ] fp16
__device__ unsigned short g_ENCh[4096u * 4096u];  // attention output fp16
__device__ float          g_ts  [128];            // RoPE timescales (powf table)

// ---------------- helpers -----------------------------------------------------
__device__ __forceinline__ uint32_t smem_u32(const void* p) {
    uint32_t a;
    asm("{ .reg .u64 t; cvta.to.shared.u64 t, %1; cvt.u32.u64 %0, t; }" : "=r"(a) : "l"(p));
    return a;
}
__device__ __forceinline__ void ldsm4(uint32_t* d, uint32_t addr) {
    asm volatile("ldmatrix.sync.aligned.m8n8.x4.shared.b16 {%0,%1,%2,%3}, [%4];"
                 : "=r"(d[0]), "=r"(d[1]), "=r"(d[2]), "=r"(d[3]) : "r"(addr));
}
__device__ __forceinline__ void ldsm4t(uint32_t* d, uint32_t addr) {
    asm volatile("ldmatrix.sync.aligned.m8n8.x4.trans.shared.b16 {%0,%1,%2,%3}, [%4];"
                 : "=r"(d[0]), "=r"(d[1]), "=r"(d[2]), "=r"(d[3]) : "r"(addr));
}
__device__ __forceinline__ void mma16816(float* c, const uint32_t* a, uint32_t b0, uint32_t b1) {
    asm volatile("mma.sync.aligned.m16n8k16.row.col.f32.f16.f16.f32 "
                 "{%0,%1,%2,%3}, {%4,%5,%6,%7}, {%8,%9}, {%0,%1,%2,%3};"
                 : "+f"(c[0]), "+f"(c[1]), "+f"(c[2]), "+f"(c[3])
                 : "r"(a[0]), "r"(a[1]), "r"(a[2]), "r"(a[3]), "r"(b0), "r"(b1));
}
__device__ __forceinline__ uint32_t f22u(float a, float b) {
    __half2 h = __floats2half2_rn(a, b);
    return *(uint32_t*)&h;
}
__device__ __forceinline__ void cpa16(uint32_t dst, const void* src) {
    asm volatile("cp.async.cg.shared.global [%0], [%1], 16;" :: "r"(dst), "l"(src));
}

// ---------------- fused prep: conv_x + pack_wt + pack_owt + ts table ----------
__global__ __launch_bounds__(256) void prep_all(const float* __restrict__ x,
                                                const float* __restrict__ qw,
                                                const float* __restrict__ kvw,
                                                const float* __restrict__ ow)
{
    __shared__ float t[32][33];
    const int blk = blockIdx.x;
    const int c  = threadIdx.x & 31;
    const int r0 = threadIdx.x >> 5;

    if (blk < 14336) {
        size_t i = ((size_t)blk * 256 + threadIdx.x) * 4;
        float4 v = *(const float4*)(x + i);
        uint2 u = make_uint2(f22u(v.x, v.y), f22u(v.z, v.w));
        *(uint2*)((__half*)g_Xh + i) = u;
    } else if (blk < 43008) {
        int lin = blk - 14336;
        int hd  = lin / 896;
        int rem = lin - hd * 896;
        int h0  = (rem / 112) << 5;
        int d0  = (rem % 112) << 5;
        const float* src = (hd < 16) ? (qw + (size_t)hd * 3584 * 256)
                                     : (kvw + (size_t)(hd - 16) * 3584 * 256);
#pragma unroll
        for (int r = r0; r < 32; r += 8)
            t[r][c] = src[(size_t)(d0 + r) * 256 + h0 + c];
        __syncthreads();
#pragma unroll
        for (int r = r0; r < 32; r += 8)
            g_Wth[(size_t)(hd * 256 + h0 + r) * 3584 + d0 + c] =
                __half_as_ushort(__float2half(t[c][r]));
    } else if (blk < 57344) {
        int lin = blk - 43008;
        int j0  = (lin % 128) << 5;
        int d0  = (lin / 128) << 5;
#pragma unroll
        for (int r = r0; r < 32; r += 8)
            t[r][c] = ow[(size_t)(j0 + r) * 3584 + d0 + c];
        __syncthreads();
#pragma unroll
        for (int r = r0; r < 32; r += 8)
            g_OWth[(size_t)(d0 + r) * 4096 + j0 + c] =
                __half_as_ushort(__float2half(t[c][r]));
    } else {
        int i = threadIdx.x;
        if (i < 128)
            g_ts[i] = powf(10000.0f, (float)i * (1.0f / 128.0f));
    }
}

// ------ fp16 HMMA GEMM: R14 config (128x128 CTA, 32x64 warp, 4-stage, supertile)
#define PITCH 40
#define STAGE_B 20480
#define NSTG 4
#define HGEMM_SMEM (NSTG * STAGE_B)      // 81920 B -> 2 CTAs/SM

template <typename CT>
__global__ __launch_bounds__(256, 2) void hgemm(const __half* __restrict__ A,
                                                const __half* __restrict__ B,
                                                CT* __restrict__ C,
                                                int Nout, int Kdim)
{
    extern __shared__ __half hsm[];

    const int tid  = threadIdx.x;
    const int lane = tid & 31;
    const int wid  = tid >> 5;
    const int wm = (wid & 3) << 5;
    const int wn = (wid >> 2) << 6;

    const int lin = blockIdx.y * gridDim.x + blockIdx.x;
    const int tpg = gridDim.x << 3;
    const int grp = lin / tpg;
    const int rem = lin - grp * tpg;
    const int m0 = ((grp << 3) + (rem & 7)) << 7;
    const int n0 = (rem >> 3) << 7;

    const int nk = Kdim >> 5;

    const int lrow = tid >> 1;
    const int lcol = (tid & 1) << 4;
    const __half* ag = A + (size_t)(m0 + lrow) * Kdim + lcol;
    const __half* bg = B + (size_t)(n0 + lrow) * Kdim + lcol;

    uint32_t sb  = smem_u32(hsm);
    uint32_t sa  = sb + (uint32_t)(lrow * PITCH + lcol) * 2;
    uint32_t sbq = sa + 10240;

    const uint32_t lq = lane & 15;
    const uint32_t lh = (lane >> 4) << 4;
    uint32_t abase = sb + ((wm + lq) * PITCH) * 2 + lh;
    uint32_t bbase = sb + 10240 + ((wn + lq) * PITCH) * 2 + lh;

    float acc[2][8][4];
#pragma unroll
    for (int i = 0; i < 2; i++)
#pragma unroll
        for (int j = 0; j < 8; j++)
#pragma unroll
            for (int q = 0; q < 4; q++) acc[i][j][q] = 0.f;

#define HLOAD(i, s) do {                                                          \
    uint32_t _da = sa + (uint32_t)(s) * STAGE_B;                                  \
    uint32_t _db = sbq + (uint32_t)(s) * STAGE_B;                                 \
    const __half* _a = ag + ((i) << 5);                                           \
    const __half* _b = bg + ((i) << 5);                                           \
    asm volatile("cp.async.cg.shared.global [%0], [%1], 16;\n\t"                  \
                 "cp.async.cg.shared.global [%2], [%3], 16;\n\t"                  \
                 "cp.async.cg.shared.global [%4], [%5], 16;\n\t"                  \
                 "cp.async.cg.shared.global [%6], [%7], 16;\n\t"                  \
                 "cp.async.commit_group;"                                         \
                 :: "r"(_da), "l"(_a), "r"(_da + 16), "l"(_a + 8),                \
                    "r"(_db), "l"(_b), "r"(_db + 16), "l"(_b + 8));               \
} while (0)

    HLOAD(0, 0);
    HLOAD(1, 1);
    HLOAD(2, 2);

    for (int i = 0; i < nk; i++) {
        if (i < nk - 2)       asm volatile("cp.async.wait_group 2;");
        else if (i == nk - 2) asm volatile("cp.async.wait_group 1;");
        else                  asm volatile("cp.async.wait_group 0;");
        __syncthreads();
        if (i + 3 < nk) HLOAD(i + 3, (i + 3) & 3);

        uint32_t so = (uint32_t)(i & 3) * STAGE_B;
        uint32_t ab = abase + so;
        uint32_t bb = bbase + so;
#pragma unroll
        for (int ks = 0; ks < 2; ks++) {
            uint32_t af[2][4], bf[4][4];
            ldsm4(af[0], ab + ks * 32);
            ldsm4(af[1], ab + 16 * PITCH * 2 + ks * 32);
#pragma unroll
            for (int p = 0; p < 4; p++)
                ldsm4(bf[p], bb + p * (16 * PITCH * 2) + ks * 32);
#pragma unroll
            for (int mt = 0; mt < 2; mt++)
#pragma unroll
                for (int p = 0; p < 4; p++) {
                    mma16816(acc[mt][2 * p],     af[mt], bf[p][0], bf[p][2]);
                    mma16816(acc[mt][2 * p + 1], af[mt], bf[p][1], bf[p][3]);
                }
        }
    }

    const int g  = lane >> 2;
    const int cc = (lane & 3) << 1;
#pragma unroll
    for (int mt = 0; mt < 2; mt++) {
        int r = m0 + wm + mt * 16 + g;
#pragma unroll
        for (int nt = 0; nt < 8; nt++) {
            size_t off = (size_t)r * Nout + n0 + wn + nt * 8 + cc;
            if (sizeof(CT) == 2) {
                __half* cp = (__half*)C + off;
                *(uint32_t*)cp = f22u(acc[mt][nt][0], acc[mt][nt][1]);
                *(uint32_t*)(cp + (size_t)8 * Nout) = f22u(acc[mt][nt][2], acc[mt][nt][3]);
            } else {
                float* cp = (float*)C + off;
                *(float2*)cp = make_float2(acc[mt][nt][0], acc[mt][nt][1]);
                *(float2*)(cp + (size_t)8 * Nout) = make_float2(acc[mt][nt][2], acc[mt][nt][3]);
            }
        }
    }
}

// ---------------- RoPE (+ q scaling), table-based timescale -------------------
__global__ __launch_bounds__(128) void rope_kernel(const int* __restrict__ segpos)
{
    int bt = blockIdx.x;
    int hh = blockIdx.y;
    int i  = threadIdx.x;
    __half* p = (__half*)g_QKVh + (size_t)bt * 8192 + hh * 256;
    float pos = (float)segpos[bt];
    float ts  = g_ts[i];
    float ang = pos / ts;
    float s, c;
    sincosf(ang, &s, &c);
    float a  = __half2float(p[i]);
    float b2 = __half2float(p[i + 128]);
    float o1 = a * c - b2 * s;
    float o2 = b2 * c + a * s;
    if (hh < 16) { o1 *= 0.0625f; o2 *= 0.0625f; }
    p[i]       = __float2half(o1);
    p[i + 128] = __float2half(o2);
}

// ---------------- fp16 tensor-core flash attention (R10/R14, unchanged) -------
#define APITCH 264
#define KS_OFF (128 * APITCH)
#define KS_SZ  (64 * APITCH)
#define VS_OFF (KS_OFF + 2 * KS_SZ)
#define ATTN_SMEM ((KS_OFF + 4 * KS_SZ) * 2)   // 202752 bytes

__global__ __launch_bounds__(256, 1) void attn_kernel()
{
    extern __shared__ __half ash[];
    const int tid  = threadIdx.x;
    const int lane = tid & 31;
    const int w    = tid >> 5;
    const int t0   = (15 - blockIdx.x) << 7;   // heavy tiles scheduled first
    const int n    = blockIdx.y;
    const int b    = blockIdx.z;
    const int kh   = n >> 1;
    uint32_t sb = smem_u32(ash);

    const __half* qkvh = (const __half*)g_QKVh + (size_t)b * 2048 * 8192;

    {
        const __half* qs = qkvh + (size_t)t0 * 8192 + n * 256;
#pragma unroll
        for (int it = 0; it < 16; it++) {
            int slot = it * 256 + tid;
            int r = slot >> 5, cs = (slot & 31) << 3;
            cpa16(sb + (r * APITCH + cs) * 2, qs + (size_t)r * 8192 + cs);
        }
    }

    int smin = t0 - 1023; if (smin < 0) smin = 0;
    const int c0 = smin >> 6, c1 = (t0 + 127) >> 6;

    const int ldr = tid >> 5, ldc = (tid & 31) << 3;

#define LOADKV(sg0, bf) do {                                                       \
    const __half* _ks = qkvh + (size_t)(sg0) * 8192 + 4096 + kh * 256;             \
    uint32_t _kb = sb + (KS_OFF + (bf) * KS_SZ) * 2;                               \
    uint32_t _vb = sb + (VS_OFF + (bf) * KS_SZ) * 2;                               \
    _Pragma("unroll")                                                              \
    for (int _it = 0; _it < 8; _it++) {                                            \
        int _r = _it * 8 + ldr;                                                    \
        cpa16(_kb + (_r * APITCH + ldc) * 2, _ks + (size_t)_r * 8192 + ldc);       \
        cpa16(_vb + (_r * APITCH + ldc) * 2, _ks + (size_t)_r * 8192 + 2048 + ldc);\
    }                                                                              \
    asm volatile("cp.async.commit_group;");                                        \
} while (0)

    LOADKV(c0 << 6, 0);

    float of[32][4];
#pragma unroll
    for (int f = 0; f < 32; f++)
#pragma unroll
        for (int q = 0; q < 4; q++) of[f][q] = 0.f;
    float m0 = -1e30f, m1 = -1e30f, l0 = 0.f, l1 = 0.f;

    const uint32_t lq  = lane & 15;
    const uint32_t lh16 = (lane >> 4) << 4;
    uint32_t qb  = sb + (((w << 4) + lq) * APITCH) * 2 + lh16;
    uint32_t kvl = (lq * APITCH) * 2 + lh16;

    const int row0 = t0 + (w << 4) + (lane >> 2);
    const int row1 = row0 + 8;
    const int colq = (lane & 3) << 1;
    const int wr0 = t0 + (w << 4), wr1 = wr0 + 15;

    int buf = 0;
    for (int c = c0; c <= c1; c++) {
        const int sg0 = c << 6;
        if (c < c1) {
            LOADKV((c + 1) << 6, buf ^ 1);
            asm volatile("cp.async.wait_group 1;");
        } else {
            asm volatile("cp.async.wait_group 0;");
        }
        __syncthreads();

        if (sg0 <= wr1 && sg0 + 63 >= wr0 - 1023) {
            uint32_t kb = sb + (KS_OFF + buf * KS_SZ) * 2 + kvl;
            uint32_t vb = sb + (VS_OFF + buf * KS_SZ) * 2 + kvl;

            float sf[8][4];
#pragma unroll
            for (int j = 0; j < 8; j++)
#pragma unroll
                for (int q = 0; q < 4; q++) sf[j][q] = 0.f;

#pragma unroll
            for (int kk = 0; kk < 16; kk++) {
                uint32_t a[4];
                ldsm4(a, qb + kk * 32);
#pragma unroll
                for (int ng = 0; ng < 4; ng++) {
                    uint32_t bfr[4];
                    ldsm4(bfr, kb + ng * (16 * APITCH * 2) + kk * 32);
                    mma16816(sf[ng * 2],     a, bfr[0], bfr[2]);
                    mma16816(sf[ng * 2 + 1], a, bfr[1], bfr[3]);
                }
            }

            float mx0 = -1e30f, mx1 = -1e30f;
#pragma unroll
            for (int j = 0; j < 8; j++) {
                int col = sg0 + j * 8 + colq;
#pragma unroll
                for (int q = 0; q < 4; q++) {
                    float e = __expf(sf[j][q] * 0.04f);
                    float s = 50.f * __fdividef(e - 1.f, e + 1.f);
                    int rr = (q < 2) ? row0 : row1;
                    int cc2 = col + (q & 1);
                    bool ok = (cc2 <= rr) && (cc2 >= rr - 1023);
                    sf[j][q] = ok ? s : -1e30f;
                }
                mx0 = fmaxf(mx0, fmaxf(sf[j][0], sf[j][1]));
                mx1 = fmaxf(mx1, fmaxf(sf[j][2], sf[j][3]));
            }
            mx0 = fmaxf(mx0, __shfl_xor_sync(~0u, mx0, 1));
            mx0 = fmaxf(mx0, __shfl_xor_sync(~0u, mx0, 2));
            mx1 = fmaxf(mx1, __shfl_xor_sync(~0u, mx1, 1));
            mx1 = fmaxf(mx1, __shfl_xor_sync(~0u, mx1, 2));

            float mn0 = fmaxf(m0, mx0), mn1 = fmaxf(m1, mx1);
            float a0 = __expf(m0 - mn0), a1 = __expf(m1 - mn1);
            m0 = mn0; m1 = mn1;

            float rs0 = 0.f, rs1 = 0.f;
#pragma unroll
            for (int j = 0; j < 8; j++) {
                sf[j][0] = __expf(sf[j][0] - mn0); rs0 += sf[j][0];
                sf[j][1] = __expf(sf[j][1] - mn0); rs0 += sf[j][1];
                sf[j][2] = __expf(sf[j][2] - mn1); rs1 += sf[j][2];
                sf[j][3] = __expf(sf[j][3] - mn1); rs1 += sf[j][3];
            }
            rs0 += __shfl_xor_sync(~0u, rs0, 1);
            rs0 += __shfl_xor_sync(~0u, rs0, 2);
            rs1 += __shfl_xor_sync(~0u, rs1, 1);
            rs1 += __shfl_xor_sync(~0u, rs1, 2);
            l0 = l0 * a0 + rs0;
            l1 = l1 * a1 + rs1;

#pragma unroll
            for (int f = 0; f < 32; f++) {
                of[f][0] *= a0; of[f][1] *= a0;
                of[f][2] *= a1; of[f][3] *= a1;
            }

            uint32_t pa[4][4];
#pragma unroll
            for (int sj = 0; sj < 4; sj++) {
                pa[sj][0] = f22u(sf[2 * sj][0],     sf[2 * sj][1]);
                pa[sj][1] = f22u(sf[2 * sj][2],     sf[2 * sj][3]);
                pa[sj][2] = f22u(sf[2 * sj + 1][0], sf[2 * sj + 1][1]);
                pa[sj][3] = f22u(sf[2 * sj + 1][2], sf[2 * sj + 1][3]);
            }

#pragma unroll
            for (int sj = 0; sj < 4; sj++) {
#pragma unroll
                for (int hg = 0; hg < 16; hg++) {
                    uint32_t v[4];
                    ldsm4t(v, vb + sj * (16 * APITCH * 2) + hg * 32);
                    mma16816(of[hg * 2],     pa[sj], v[0], v[1]);
                    mma16816(of[hg * 2 + 1], pa[sj], v[2], v[3]);
                }
            }
        }
        __syncthreads();
        buf ^= 1;
    }

    float i0 = 1.f / l0, i1 = 1.f / l1;
    __half* ENC = (__half*)g_ENCh;
    size_t base0 = ((size_t)(b * 2048) + row0) * 4096 + n * 256 + colq;
    size_t base1 = ((size_t)(b * 2048) + row1) * 4096 + n * 256 + colq;
#pragma unroll
    for (int f = 0; f < 32; f++) {
        *(uint32_t*)(ENC + base0 + f * 8) = f22u(of[f][0] * i0, of[f][1] * i0);
        *(uint32_t*)(ENC + base1 + f * 8) = f22u(of[f][2] * i1, of[f][3] * i1);
    }
}

// ---------------- launch (single-stream schedule) -------------------------------
extern "C" void kernel_launch(void* const* d_in, const int* in_sizes, int n_in,
                              void* d_out, int out_size)
{
    const float* x      = (const float*)d_in[0];
    const int*   segpos = (const int*)  d_in[1];
    const float* qw     = (const float*)d_in[3];
    const float* kvw    = (const float*)d_in[4];
    const float* ow     = (const float*)d_in[5];
    float* out = (float*)d_out;

    void *Xh, *Wth, *OWth, *QKVh, *ENCh;
    cudaGetSymbolAddress(&Xh,   g_Xh);
    cudaGetSymbolAddress(&Wth,  g_Wth);
    cudaGetSymbolAddress(&OWth, g_OWth);
    cudaGetSymbolAddress(&QKVh, g_QKVh);
    cudaGetSymbolAddress(&ENCh, g_ENCh);

    // fused prep: conv_x + pack_wt + pack_owt + ts table (one launch)
    prep_all<<<57345, 256>>>(x, qw, kvw, ow);

    cudaFuncSetAttribute(hgemm<__half>, cudaFuncAttributeMaxDynamicSharedMemorySize, HGEMM_SMEM);
    cudaFuncSetAttribute(hgemm<float>,  cudaFuncAttributeMaxDynamicSharedMemorySize, HGEMM_SMEM);
    cudaFuncSetAttribute(attn_kernel,   cudaFuncAttributeMaxDynamicSharedMemorySize, ATTN_SMEM);

    // qkv = x @ Wt^T -> fp16  (M=4096, N=8192, K=3584)
    hgemm<__half><<<dim3(8192 / 128, 4096 / 128), 256, HGEMM_SMEM>>>(
        (const __half*)Xh, (const __half*)Wth, (__half*)QKVh, 8192, 3584);

    // RoPE + q scaling in place (fp16, table-based timescales)
    rope_kernel<<<dim3(4096, 24), 128>>>(segpos);

    // fp16 flash attention -> ENCh (heavy-first tile order)
    attn_kernel<<<dim3(16, 16, 2), 256, ATTN_SMEM>>>();

    // out = ENC @ OWt^T -> fp32  (M=4096, N=3584, K=4096)
    hgemm<float><<<dim3(3584 / 128, 4096 / 128), 256, HGEMM_SMEM>>>(
        (const __half*)ENCh, (const __half*)OWth, out, 3584, 4096);
}

// round 17
// speedup vs baseline: 1.0466x; 1.0198x over previous
#include <cuda_runtime.h>
#include <cuda_fp16.h>
#include <math.h>
#include <stdint.h>

// B=2, T=2048, D=3584, N=16, K=8, H=256, WINDOW=1024, SOFT_CAP=50, SCALAR=0.0625

// ---------------- scratch (allocation-free device globals) -------------------
__device__ unsigned short g_Xh  [4096u * 3584u];  // x fp16
__device__ unsigned short g_Wth [8192u * 3584u];  // qkv weight [j][d] K-major fp16
__device__ unsigned short g_OWth[3584u * 4096u];  // o_w^T [d][j] K-major fp16
__device__ unsigned short g_QKVh[4096u * 8192u];  // [B*T][ q | k | v ] fp16
__device__ unsigned short g_ENCh[4096u * 4096u];  // attention output fp16
__device__ float2         g_sc  [4096u * 128u];   // RoPE (sin,cos) per (bt, i)

// ---------------- helpers -----------------------------------------------------
__device__ __forceinline__ uint32_t smem_u32(const void* p) {
    uint32_t a;
    asm("{ .reg .u64 t; cvta.to.shared.u64 t, %1; cvt.u32.u64 %0, t; }" : "=r"(a) : "l"(p));
    return a;
}
__device__ __forceinline__ void ldsm4(uint32_t* d, uint32_t addr) {
    asm volatile("ldmatrix.sync.aligned.m8n8.x4.shared.b16 {%0,%1,%2,%3}, [%4];"
                 : "=r"(d[0]), "=r"(d[1]), "=r"(d[2]), "=r"(d[3]) : "r"(addr));
}
__device__ __forceinline__ void ldsm4t(uint32_t* d, uint32_t addr) {
    asm volatile("ldmatrix.sync.aligned.m8n8.x4.trans.shared.b16 {%0,%1,%2,%3}, [%4];"
                 : "=r"(d[0]), "=r"(d[1]), "=r"(d[2]), "=r"(d[3]) : "r"(addr));
}
__device__ __forceinline__ void mma16816(float* c, const uint32_t* a, uint32_t b0, uint32_t b1) {
    asm volatile("mma.sync.aligned.m16n8k16.row.col.f32.f16.f16.f32 "
                 "{%0,%1,%2,%3}, {%4,%5,%6,%7}, {%8,%9}, {%0,%1,%2,%3};"
                 : "+f"(c[0]), "+f"(c[1]), "+f"(c[2]), "+f"(c[3])
                 : "r"(a[0]), "r"(a[1]), "r"(a[2]), "r"(a[3]), "r"(b0), "r"(b1));
}
__device__ __forceinline__ uint32_t f22u(float a, float b) {
    __half2 h = __floats2half2_rn(a, b);
    return *(uint32_t*)&h;
}
__device__ __forceinline__ void cpa16(uint32_t dst, const void* src) {
    asm volatile("cp.async.cg.shared.global [%0], [%1], 16;" :: "r"(dst), "l"(src));
}

// ---------------- prep main: conv_x + pack_wt + sincos table ------------------
//   [0, 14336)       conv_x   (float4 per thread)
//   [14336, 43008)   pack_wt  (32x32 tile transpose)
//   [43008, 47104)   RoPE sin/cos table: bt = blk-43008, i = tid (<128)
__global__ __launch_bounds__(256) void prep_main(const float* __restrict__ x,
                                                 const float* __restrict__ qw,
                                                 const float* __restrict__ kvw,
                                                 const int*   __restrict__ segpos)
{
    __shared__ float t[32][33];
    const int blk = blockIdx.x;
    const int c  = threadIdx.x & 31;
    const int r0 = threadIdx.x >> 5;

    if (blk < 14336) {
        size_t i = ((size_t)blk * 256 + threadIdx.x) * 4;
        float4 v = *(const float4*)(x + i);
        uint2 u = make_uint2(f22u(v.x, v.y), f22u(v.z, v.w));
        *(uint2*)((__half*)g_Xh + i) = u;
    } else if (blk < 43008) {
        int lin = blk - 14336;
        int hd  = lin / 896;
        int rem = lin - hd * 896;
        int h0  = (rem / 112) << 5;
        int d0  = (rem % 112) << 5;
        const float* src = (hd < 16) ? (qw + (size_t)hd * 3584 * 256)
                                     : (kvw + (size_t)(hd - 16) * 3584 * 256);
#pragma unroll
        for (int r = r0; r < 32; r += 8)
            t[r][c] = src[(size_t)(d0 + r) * 256 + h0 + c];
        __syncthreads();
#pragma unroll
        for (int r = r0; r < 32; r += 8)
            g_Wth[(size_t)(hd * 256 + h0 + r) * 3584 + d0 + c] =
                __half_as_ushort(__float2half(t[c][r]));
    } else {
        // sin/cos table: identical math chain to the original rope kernel
        // (powf timescale -> pos/ts -> sincosf), computed once per (bt, i).
        int bt = blk - 43008;
        int i  = threadIdx.x;
        if (i < 128) {
            float ts  = powf(10000.0f, (float)i * (1.0f / 128.0f));
            float pos = (float)segpos[bt];
            float s, cc;
            sincosf(pos / ts, &s, &cc);
            g_sc[bt * 128 + i] = make_float2(s, cc);
        }
    }
}

// ---------------- prep B: pack_owt (side stream; joined before hgemm2) --------
__global__ __launch_bounds__(256) void prep_owt(const float* __restrict__ ow)
{
    __shared__ float t[32][33];
    const int c  = threadIdx.x & 31;
    const int r0 = threadIdx.x >> 5;
    int j0 = (blockIdx.x % 128) << 5;
    int d0 = (blockIdx.x / 128) << 5;
#pragma unroll
    for (int r = r0; r < 32; r += 8)
        t[r][c] = ow[(size_t)(j0 + r) * 3584 + d0 + c];
    __syncthreads();
#pragma unroll
    for (int r = r0; r < 32; r += 8)
        g_OWth[(size_t)(d0 + r) * 4096 + j0 + c] =
            __half_as_ushort(__float2half(t[c][r]));
}

// ------ fp16 HMMA GEMM: R14 config (128x128 CTA, 32x64 warp, 4-stage, supertile)
#define PITCH 40
#define STAGE_B 20480
#define NSTG 4
#define HGEMM_SMEM (NSTG * STAGE_B)      // 81920 B -> 2 CTAs/SM

template <typename CT>
__global__ __launch_bounds__(256, 2) void hgemm(const __half* __restrict__ A,
                                                const __half* __restrict__ B,
                                                CT* __restrict__ C,
                                                int Nout, int Kdim)
{
    extern __shared__ __half hsm[];

    const int tid  = threadIdx.x;
    const int lane = tid & 31;
    const int wid  = tid >> 5;
    const int wm = (wid & 3) << 5;
    const int wn = (wid >> 2) << 6;

    const int lin = blockIdx.y * gridDim.x + blockIdx.x;
    const int tpg = gridDim.x << 3;
    const int grp = lin / tpg;
    const int rem = lin - grp * tpg;
    const int m0 = ((grp << 3) + (rem & 7)) << 7;
    const int n0 = (rem >> 3) << 7;

    const int nk = Kdim >> 5;

    const int lrow = tid >> 1;
    const int lcol = (tid & 1) << 4;
    const __half* ag = A + (size_t)(m0 + lrow) * Kdim + lcol;
    const __half* bg = B + (size_t)(n0 + lrow) * Kdim + lcol;

    uint32_t sb  = smem_u32(hsm);
    uint32_t sa  = sb + (uint32_t)(lrow * PITCH + lcol) * 2;
    uint32_t sbq = sa + 10240;

    const uint32_t lq = lane & 15;
    const uint32_t lh = (lane >> 4) << 4;
    uint32_t abase = sb + ((wm + lq) * PITCH) * 2 + lh;
    uint32_t bbase = sb + 10240 + ((wn + lq) * PITCH) * 2 + lh;

    float acc[2][8][4];
#pragma unroll
    for (int i = 0; i < 2; i++)
#pragma unroll
        for (int j = 0; j < 8; j++)
#pragma unroll
            for (int q = 0; q < 4; q++) acc[i][j][q] = 0.f;

#define HLOAD(i, s) do {                                                          \
    uint32_t _da = sa + (uint32_t)(s) * STAGE_B;                                  \
    uint32_t _db = sbq + (uint32_t)(s) * STAGE_B;                                 \
    const __half* _a = ag + ((i) << 5);                                           \
    const __half* _b = bg + ((i) << 5);                                           \
    asm volatile("cp.async.cg.shared.global [%0], [%1], 16;\n\t"                  \
                 "cp.async.cg.shared.global [%2], [%3], 16;\n\t"                  \
                 "cp.async.cg.shared.global [%4], [%5], 16;\n\t"                  \
                 "cp.async.cg.shared.global [%6], [%7], 16;\n\t"                  \
                 "cp.async.commit_group;"                                         \
                 :: "r"(_da), "l"(_a), "r"(_da + 16), "l"(_a + 8),                \
                    "r"(_db), "l"(_b), "r"(_db + 16), "l"(_b + 8));               \
} while (0)

    HLOAD(0, 0);
    HLOAD(1, 1);
    HLOAD(2, 2);

    for (int i = 0; i < nk; i++) {
        if (i < nk - 2)       asm volatile("cp.async.wait_group 2;");
        else if (i == nk - 2) asm volatile("cp.async.wait_group 1;");
        else                  asm volatile("cp.async.wait_group 0;");
        __syncthreads();
        if (i + 3 < nk) HLOAD(i + 3, (i + 3) & 3);

        uint32_t so = (uint32_t)(i & 3) * STAGE_B;
        uint32_t ab = abase + so;
        uint32_t bb = bbase + so;
#pragma unroll
        for (int ks = 0; ks < 2; ks++) {
            uint32_t af[2][4], bf[4][4];
            ldsm4(af[0], ab + ks * 32);
            ldsm4(af[1], ab + 16 * PITCH * 2 + ks * 32);
#pragma unroll
            for (int p = 0; p < 4; p++)
                ldsm4(bf[p], bb + p * (16 * PITCH * 2) + ks * 32);
#pragma unroll
            for (int mt = 0; mt < 2; mt++)
#pragma unroll
                for (int p = 0; p < 4; p++) {
                    mma16816(acc[mt][2 * p],     af[mt], bf[p][0], bf[p][2]);
                    mma16816(acc[mt][2 * p + 1], af[mt], bf[p][1], bf[p][3]);
                }
        }
    }

    const int g  = lane >> 2;
    const int cc = (lane & 3) << 1;
#pragma unroll
    for (int mt = 0; mt < 2; mt++) {
        int r = m0 + wm + mt * 16 + g;
#pragma unroll
        for (int nt = 0; nt < 8; nt++) {
            size_t off = (size_t)r * Nout + n0 + wn + nt * 8 + cc;
            if (sizeof(CT) == 2) {
                __half* cp = (__half*)C + off;
                *(uint32_t*)cp = f22u(acc[mt][nt][0], acc[mt][nt][1]);
                *(uint32_t*)(cp + (size_t)8 * Nout) = f22u(acc[mt][nt][2], acc[mt][nt][3]);
            } else {
                float* cp = (float*)C + off;
                *(float2*)cp = make_float2(acc[mt][nt][0], acc[mt][nt][1]);
                *(float2*)(cp + (size_t)8 * Nout) = make_float2(acc[mt][nt][2], acc[mt][nt][3]);
            }
        }
    }
}

// ---------------- RoPE (+ q scaling): table-based, half2-vectorized -----------
// One block per token row (bt). smem sin/cos reused across all 24 heads.
__global__ __launch_bounds__(256) void rope_kernel()
{
    __shared__ float2 sc[128];
    const int bt = blockIdx.x;
    if (threadIdx.x < 128) sc[threadIdx.x] = g_sc[bt * 128 + threadIdx.x];
    __syncthreads();

    __half2* base = (__half2*)((__half*)g_QKVh + (size_t)bt * 8192);
#pragma unroll
    for (int it = 0; it < 6; it++) {
        int wk   = it * 256 + threadIdx.x;   // 0..1535 = 24 heads x 64 half2-pairs
        int head = wk >> 6;
        int j    = wk & 63;
        __half2* p = base + head * 128;
        __half2 a2 = p[j];
        __half2 b2 = p[j + 64];
        float2 s0 = sc[2 * j];
        float2 s1 = sc[2 * j + 1];
        float a0 = __low2float(a2), a1 = __high2float(a2);
        float b0 = __low2float(b2), b1 = __high2float(b2);
        float o0 = a0 * s0.y - b0 * s0.x;
        float o1 = a1 * s1.y - b1 * s1.x;
        float q0 = b0 * s0.y + a0 * s0.x;
        float q1 = b1 * s1.y + a1 * s1.x;
        if (head < 16) { o0 *= 0.0625f; o1 *= 0.0625f; q0 *= 0.0625f; q1 *= 0.0625f; }
        p[j]      = __floats2half2_rn(o0, o1);
        p[j + 64] = __floats2half2_rn(q0, q1);
    }
}

// ---------------- fp16 tensor-core flash attention (R14, unchanged) -----------
#define APITCH 264
#define KS_OFF (128 * APITCH)
#define KS_SZ  (64 * APITCH)
#define VS_OFF (KS_OFF + 2 * KS_SZ)
#define ATTN_SMEM ((KS_OFF + 4 * KS_SZ) * 2)   // 202752 bytes

__global__ __launch_bounds__(256, 1) void attn_kernel()
{
    extern __shared__ __half ash[];
    const int tid  = threadIdx.x;
    const int lane = tid & 31;
    const int w    = tid >> 5;
    const int t0   = (15 - blockIdx.x) << 7;   // heavy tiles scheduled first
    const int n    = blockIdx.y;
    const int b    = blockIdx.z;
    const int kh   = n >> 1;
    uint32_t sb = smem_u32(ash);

    const __half* qkvh = (const __half*)g_QKVh + (size_t)b * 2048 * 8192;

    {
        const __half* qs = qkvh + (size_t)t0 * 8192 + n * 256;
#pragma unroll
        for (int it = 0; it < 16; it++) {
            int slot = it * 256 + tid;
            int r = slot >> 5, cs = (slot & 31) << 3;
            cpa16(sb + (r * APITCH + cs) * 2, qs + (size_t)r * 8192 + cs);
        }
    }

    int smin = t0 - 1023; if (smin < 0) smin = 0;
    const int c0 = smin >> 6, c1 = (t0 + 127) >> 6;

    const int ldr = tid >> 5, ldc = (tid & 31) << 3;

#define LOADKV(sg0, bf) do {                                                       \
    const __half* _ks = qkvh + (size_t)(sg0) * 8192 + 4096 + kh * 256;             \
    uint32_t _kb = sb + (KS_OFF + (bf) * KS_SZ) * 2;                               \
    uint32_t _vb = sb + (VS_OFF + (bf) * KS_SZ) * 2;                               \
    _Pragma("unroll")                                                              \
    for (int _it = 0; _it < 8; _it++) {                                            \
        int _r = _it * 8 + ldr;                                                    \
        cpa16(_kb + (_r * APITCH + ldc) * 2, _ks + (size_t)_r * 8192 + ldc);       \
        cpa16(_vb + (_r * APITCH + ldc) * 2, _ks + (size_t)_r * 8192 + 2048 + ldc);\
    }                                                                              \
    asm volatile("cp.async.commit_group;");                                        \
} while (0)

    LOADKV(c0 << 6, 0);

    float of[32][4];
#pragma unroll
    for (int f = 0; f < 32; f++)
#pragma unroll
        for (int q = 0; q < 4; q++) of[f][q] = 0.f;
    float m0 = -1e30f, m1 = -1e30f, l0 = 0.f, l1 = 0.f;

    const uint32_t lq  = lane & 15;
    const uint32_t lh16 = (lane >> 4) << 4;
    uint32_t qb  = sb + (((w << 4) + lq) * APITCH) * 2 + lh16;
    uint32_t kvl = (lq * APITCH) * 2 + lh16;

    const int row0 = t0 + (w << 4) + (lane >> 2);
    const int row1 = row0 + 8;
    const int colq = (lane & 3) << 1;
    const int wr0 = t0 + (w << 4), wr1 = wr0 + 15;

    int buf = 0;
    for (int c = c0; c <= c1; c++) {
        const int sg0 = c << 6;
        if (c < c1) {
            LOADKV((c + 1) << 6, buf ^ 1);
            asm volatile("cp.async.wait_group 1;");
        } else {
            asm volatile("cp.async.wait_group 0;");
        }
        __syncthreads();

        if (sg0 <= wr1 && sg0 + 63 >= wr0 - 1023) {
            uint32_t kb = sb + (KS_OFF + buf * KS_SZ) * 2 + kvl;
            uint32_t vb = sb + (VS_OFF + buf * KS_SZ) * 2 + kvl;

            float sf[8][4];
#pragma unroll
            for (int j = 0; j < 8; j++)
#pragma unroll
                for (int q = 0; q < 4; q++) sf[j][q] = 0.f;

#pragma unroll
            for (int kk = 0; kk < 16; kk++) {
                uint32_t a[4];
                ldsm4(a, qb + kk * 32);
#pragma unroll
                for (int ng = 0; ng < 4; ng++) {
                    uint32_t bfr[4];
                    ldsm4(bfr, kb + ng * (16 * APITCH * 2) + kk * 32);
                    mma16816(sf[ng * 2],     a, bfr[0], bfr[2]);
                    mma16816(sf[ng * 2 + 1], a, bfr[1], bfr[3]);
                }
            }

            float mx0 = -1e30f, mx1 = -1e30f;
#pragma unroll
            for (int j = 0; j < 8; j++) {
                int col = sg0 + j * 8 + colq;
#pragma unroll
                for (int q = 0; q < 4; q++) {
                    float e = __expf(sf[j][q] * 0.04f);
                    float s = 50.f * __fdividef(e - 1.f, e + 1.f);
                    int rr = (q < 2) ? row0 : row1;
                    int cc2 = col + (q & 1);
                    bool ok = (cc2 <= rr) && (cc2 >= rr - 1023);
                    sf[j][q] = ok ? s : -1e30f;
                }
                mx0 = fmaxf(mx0, fmaxf(sf[j][0], sf[j][1]));
                mx1 = fmaxf(mx1, fmaxf(sf[j][2], sf[j][3]));
            }
            mx0 = fmaxf(mx0, __shfl_xor_sync(~0u, mx0, 1));
            mx0 = fmaxf(mx0, __shfl_xor_sync(~0u, mx0, 2));
            mx1 = fmaxf(mx1, __shfl_xor_sync(~0u, mx1, 1));
            mx1 = fmaxf(mx1, __shfl_xor_sync(~0u, mx1, 2));

            float mn0 = fmaxf(m0, mx0), mn1 = fmaxf(m1, mx1);
            float a0 = __expf(m0 - mn0), a1 = __expf(m1 - mn1);
            m0 = mn0; m1 = mn1;

            float rs0 = 0.f, rs1 = 0.f;
#pragma unroll
            for (int j = 0; j < 8; j++) {
                sf[j][0] = __expf(sf[j][0] - mn0); rs0 += sf[j][0];
                sf[j][1] = __expf(sf[j][1] - mn0); rs0 += sf[j][1];
                sf[j][2] = __expf(sf[j][2] - mn1); rs1 += sf[j][2];
                sf[j][3] = __expf(sf[j][3] - mn1); rs1 += sf[j][3];
            }
            rs0 += __shfl_xor_sync(~0u, rs0, 1);
            rs0 += __shfl_xor_sync(~0u, rs0, 2);
            rs1 += __shfl_xor_sync(~0u, rs1, 1);
            rs1 += __shfl_xor_sync(~0u, rs1, 2);
            l0 = l0 * a0 + rs0;
            l1 = l1 * a1 + rs1;

#pragma unroll
            for (int f = 0; f < 32; f++) {
                of[f][0] *= a0; of[f][1] *= a0;
                of[f][2] *= a1; of[f][3] *= a1;
            }

            uint32_t pa[4][4];
#pragma unroll
            for (int sj = 0; sj < 4; sj++) {
                pa[sj][0] = f22u(sf[2 * sj][0],     sf[2 * sj][1]);
                pa[sj][1] = f22u(sf[2 * sj][2],     sf[2 * sj][3]);
                pa[sj][2] = f22u(sf[2 * sj + 1][0], sf[2 * sj + 1][1]);
                pa[sj][3] = f22u(sf[2 * sj + 1][2], sf[2 * sj + 1][3]);
            }

#pragma unroll
            for (int sj = 0; sj < 4; sj++) {
#pragma unroll
                for (int hg = 0; hg < 16; hg++) {
                    uint32_t v[4];
                    ldsm4t(v, vb + sj * (16 * APITCH * 2) + hg * 32);
                    mma16816(of[hg * 2],     pa[sj], v[0], v[1]);
                    mma16816(of[hg * 2 + 1], pa[sj], v[2], v[3]);
                }
            }
        }
        __syncthreads();
        buf ^= 1;
    }

    float i0 = 1.f / l0, i1 = 1.f / l1;
    __half* ENC = (__half*)g_ENCh;
    size_t base0 = ((size_t)(b * 2048) + row0) * 4096 + n * 256 + colq;
    size_t base1 = ((size_t)(b * 2048) + row1) * 4096 + n * 256 + colq;
#pragma unroll
    for (int f = 0; f < 32; f++) {
        *(uint32_t*)(ENC + base0 + f * 8) = f22u(of[f][0] * i0, of[f][1] * i0);
        *(uint32_t*)(ENC + base1 + f * 8) = f22u(of[f][2] * i1, of[f][3] * i1);
    }
}

// ---------------- launch: main chain + owt side stream -------------------------
extern "C" void kernel_launch(void* const* d_in, const int* in_sizes, int n_in,
                              void* d_out, int out_size)
{
    const float* x      = (const float*)d_in[0];
    const int*   segpos = (const int*)  d_in[1];
    const float* qw     = (const float*)d_in[3];
    const float* kvw    = (const float*)d_in[4];
    const float* ow     = (const float*)d_in[5];
    float* out = (float*)d_out;

    void *Xh, *Wth, *OWth, *QKVh, *ENCh;
    cudaGetSymbolAddress(&Xh,   g_Xh);
    cudaGetSymbolAddress(&Wth,  g_Wth);
    cudaGetSymbolAddress(&OWth, g_OWth);
    cudaGetSymbolAddress(&QKVh, g_QKVh);
    cudaGetSymbolAddress(&ENCh, g_ENCh);

    static cudaStream_t s2 = nullptr;
    static cudaEvent_t evRoot = nullptr, evOwt = nullptr;
    if (!s2) {
        cudaStreamCreateWithFlags(&s2, cudaStreamNonBlocking);
        cudaEventCreateWithFlags(&evRoot, cudaEventDisableTiming);
        cudaEventCreateWithFlags(&evOwt,  cudaEventDisableTiming);
    }

    cudaFuncSetAttribute(hgemm<__half>, cudaFuncAttributeMaxDynamicSharedMemorySize, HGEMM_SMEM);
    cudaFuncSetAttribute(hgemm<float>,  cudaFuncAttributeMaxDynamicSharedMemorySize, HGEMM_SMEM);
    cudaFuncSetAttribute(attn_kernel,   cudaFuncAttributeMaxDynamicSharedMemorySize, ATTN_SMEM);

    // fork: pack_owt on side stream (needed only by the final GEMM)
    cudaEventRecord(evRoot, 0);
    cudaStreamWaitEvent(s2, evRoot, 0);
    prep_owt<<<14336, 256, 0, s2>>>(ow);
    cudaEventRecord(evOwt, s2);

    // main chain: conv_x + pack_wt + sincos table
    prep_main<<<47104, 256>>>(x, qw, kvw, segpos);

    // qkv = x @ Wt^T -> fp16  (M=4096, N=8192, K=3584)
    hgemm<__half><<<dim3(8192 / 128, 4096 / 128), 256, HGEMM_SMEM>>>(
        (const __half*)Xh, (const __half*)Wth, (__half*)QKVh, 8192, 3584);

    // RoPE + q scaling in place (table-based, half2-vectorized)
    rope_kernel<<<4096, 256>>>();

    // fp16 flash attention -> ENCh (heavy-first tile order)
    attn_kernel<<<dim3(16, 16, 2), 256, ATTN_SMEM>>>();

    // join: OWth ready, then out = ENC @ OWt^T -> fp32
    cudaStreamWaitEvent(0, evOwt, 0);
    hgemm<float><<<dim3(3584 / 128, 4096 / 128), 256, HGEMM_SMEM>>>(
        (const __half*)ENCh, (const __half*)OWth, out, 3584, 4096);
}